// round 6
// baseline (speedup 1.0000x reference)
#include <cuda_runtime.h>
#include <cub/cub.cuh>
#include <cstdint>

// ---------------------------------------------------------------------------
// NbitTreeEncoder under JAX default x64-DISABLED semantics:
// int32 codes (Q2's <<32 vanishes), signed sort, sign-fill arithmetic shifts
// for layer shifts >= 32, left shifts >= 32 produce 0 in the bit permutation.
// Output (float32): flags[16*N], counts[16], permute[48], offset[3], scale[3].
// ---------------------------------------------------------------------------

#define NMAX 1000000
#define TB 256
#define FULLMASK 0xffffffffu

__device__ float g_min[3], g_max[3], g_off[3], g_scl[3];
__device__ int g_ones[32];                                // bits 0..31 (32..47 == 31)
__device__ int g_perm[48];
__device__ int g_counts[16];
__device__ unsigned int g_code[NMAX];                     // pre-sort (biased) codes
__device__ unsigned int g_sorted[NMAX];                   // ucode = code ^ 0x80000000
__device__ unsigned char g_L[NMAX];
__device__ int g_blk[16 * 4096];                          // per-(layer,block) bases
__device__ unsigned int g_flagsb[(size_t)16 * NMAX / 4];  // byte-packed flags
__device__ unsigned char g_temp[64 * 1024 * 1024];        // CUB scratch

// ---------------- helpers ----------------

__device__ __forceinline__ void atomicMinF(float* addr, float v) {
    if (v >= 0.0f) atomicMin((int*)addr, __float_as_int(v));
    else           atomicMax((unsigned int*)addr, __float_as_uint(v));
}
__device__ __forceinline__ void atomicMaxF(float* addr, float v) {
    if (v >= 0.0f) atomicMax((int*)addr, __float_as_int(v));
    else           atomicMin((unsigned int*)addr, __float_as_uint(v));
}

// child slot at layer l for biased code u (u = signed_code ^ 0x80000000)
__device__ __forceinline__ unsigned child_at(unsigned u, int l) {
    unsigned cb31 = ((~u) >> 31) & 1u;          // original sign bit of code
    if (l <= 4) return cb31 ? 7u : 0u;          // shift >= 33: sign-fill
    if (l == 5) return 6u * cb31 + ((u >> 30) & 1u);  // shift 30 window spans sign
    return (u >> (45 - 3 * l)) & 7u;            // shift <= 27: plain bits
}

// ---------------- kernels ----------------

__global__ void k_init() {
    int t = threadIdx.x;
    if (t < 3) {
        g_min[t] = __int_as_float(0x7f800000);   // +inf
        g_max[t] = __int_as_float(0xff800000);   // -inf
    }
    if (t < 32) g_ones[t] = 0;
}

__global__ void k_minmax(const float* __restrict__ X, int n) {
    int i = blockIdx.x * blockDim.x + threadIdx.x;
    float inf = __int_as_float(0x7f800000);
    float v0 = inf, v1 = inf, v2 = inf;
    float w0 = -inf, w1 = -inf, w2 = -inf;
    if (i < n) {
        v0 = w0 = X[3 * i + 0];
        v1 = w1 = X[3 * i + 1];
        v2 = w2 = X[3 * i + 2];
    }
    for (int o = 16; o; o >>= 1) {
        v0 = fminf(v0, __shfl_down_sync(FULLMASK, v0, o));
        v1 = fminf(v1, __shfl_down_sync(FULLMASK, v1, o));
        v2 = fminf(v2, __shfl_down_sync(FULLMASK, v2, o));
        w0 = fmaxf(w0, __shfl_down_sync(FULLMASK, w0, o));
        w1 = fmaxf(w1, __shfl_down_sync(FULLMASK, w1, o));
        w2 = fmaxf(w2, __shfl_down_sync(FULLMASK, w2, o));
    }
    __shared__ float s[8][6];
    int lane = threadIdx.x & 31, wid = threadIdx.x >> 5;
    if (lane == 0) {
        s[wid][0] = v0; s[wid][1] = v1; s[wid][2] = v2;
        s[wid][3] = w0; s[wid][4] = w1; s[wid][5] = w2;
    }
    __syncthreads();
    if (threadIdx.x == 0) {
        int nw = (blockDim.x + 31) >> 5;
        for (int w = 1; w < nw; w++) {
            s[0][0] = fminf(s[0][0], s[w][0]);
            s[0][1] = fminf(s[0][1], s[w][1]);
            s[0][2] = fminf(s[0][2], s[w][2]);
            s[0][3] = fmaxf(s[0][3], s[w][3]);
            s[0][4] = fmaxf(s[0][4], s[w][4]);
            s[0][5] = fmaxf(s[0][5], s[w][5]);
        }
        atomicMinF(&g_min[0], s[0][0]);
        atomicMinF(&g_min[1], s[0][1]);
        atomicMinF(&g_min[2], s[0][2]);
        atomicMaxF(&g_max[0], s[0][3]);
        atomicMaxF(&g_max[1], s[0][4]);
        atomicMaxF(&g_max[2], s[0][5]);
    }
}

__global__ void k_params() {
    int a = threadIdx.x;
    if (a < 3) {
        float off = -g_min[a];
        g_off[a] = off;
        float m = g_max[a] + off;                 // == max(X+offset), monotone FP
        g_scl[a] = 65535.0f / (m == 0.0f ? 1.0f : m);
    }
}

// quantize + pack to int32 code (Q2 dropped: <<32 -> 0) + per-bit popcount
__global__ void k_quant(const float* __restrict__ X, int n) {
    __shared__ int hist[32];
    if (threadIdx.x < 32) hist[threadIdx.x] = 0;
    __syncthreads();

    int i = blockIdx.x * blockDim.x + threadIdx.x;
    unsigned c = 0;
    if (i < n) {
        unsigned q0 = (unsigned)(int)rintf((X[3 * i + 0] + g_off[0]) * g_scl[0]);
        unsigned q1 = (unsigned)(int)rintf((X[3 * i + 1] + g_off[1]) * g_scl[1]);
        // axis 2 contributes Q2 << 32 == 0 under int32 (XLA saturating shift)
        c = q0 + (q1 << 16);
        g_code[i] = c;
    }
    int lane = threadIdx.x & 31;
    #pragma unroll
    for (int j = 0; j < 32; j++) {
        unsigned bal = __ballot_sync(FULLMASK, (int)((c >> j) & 1u));
        if (lane == 0 && bal) atomicAdd(&hist[j], __popc(bal));
    }
    __syncthreads();
    if (threadIdx.x < 32 && hist[threadIdx.x])
        atomicAdd(&g_ones[threadIdx.x], hist[threadIdx.x]);
}

// stable argsort ascending of score = max(ones, n-ones); ones[32..47]=ones[31]
__global__ void k_perm(int n) {
    if (threadIdx.x == 0 && blockIdx.x == 0) {
        long long score[48];
        bool used[48];
        for (int j = 0; j < 48; j++) {
            long long o = (long long)g_ones[j < 32 ? j : 31];
            long long s2 = (long long)n - o;
            score[j] = o > s2 ? o : s2;
            used[j] = false;
        }
        for (int k = 0; k < 48; k++) {
            int best = -1;
            for (int j = 0; j < 48; j++)
                if (!used[j] && (best < 0 || score[j] < score[best])) best = j;
            used[best] = true;
            g_perm[k] = best;   // p[k] = argsort(score)[k] (stable)
        }
    }
}

// bit j -> position p[j]; destinations >= 32 vanish (int32 left shift);
// source bits j >= 32 read the sign bit (arithmetic right shift fill).
// Then bias for signed sort: ucode = code ^ 0x80000000.
__global__ void k_remap(int n) {
    __shared__ int sp[48];
    if (threadIdx.x < 48) sp[threadIdx.x] = g_perm[threadIdx.x];
    __syncthreads();
    int i = blockIdx.x * blockDim.x + threadIdx.x;
    if (i < n) {
        unsigned c = g_code[i];
        unsigned sign = (c >> 31) & 1u;
        unsigned nc = 0;
        #pragma unroll
        for (int j = 0; j < 48; j++) {
            int d = sp[j];
            if (d <= 31) {
                unsigned bit = (j <= 31) ? ((c >> j) & 1u) : sign;
                nc |= bit << d;
            }
        }
        g_code[i] = nc ^ 0x80000000u;   // biased: unsigned order == signed order
    }
}

// L[i]: smallest layer l (1..16) at which sorted[i] starts a new group; 17 if dup.
// Grouping at layer l: l<=5 -> by sign only; l>=6 -> by bits [31 : 48-3l].
__global__ void k_L(int n) {
    int i = blockIdx.x * blockDim.x + threadIdx.x;
    if (i >= n) return;
    int L = 17;
    if (i > 0) {
        unsigned d = g_sorted[i] ^ g_sorted[i - 1];
        if (d) {
            int hb = 31 - __clz(d);
            L = (hb == 31) ? 1 : (50 - hb) / 3;   // ceil((48-hb)/3)
        }
    }
    g_L[i] = (unsigned char)L;
}

// per-block histogram of L -> per-(layer,block) counts of (L <= l)
__global__ void k_blkcnt(int n, int B) {
    __shared__ int hist[18];
    if (threadIdx.x < 18) hist[threadIdx.x] = 0;
    __syncthreads();
    int i = blockIdx.x * TB + threadIdx.x;
    if (i < n) atomicAdd(&hist[g_L[i]], 1);
    __syncthreads();
    if (threadIdx.x < 16) {
        int s = 0;
        for (int k = 1; k <= threadIdx.x; k++) s += hist[k];
        g_blk[threadIdx.x * B + blockIdx.x] = s;
    }
}

// exclusive scan over blocks per layer (grid = 16 blocks, one per layer)
__global__ void k_blkscan(int B) {
    typedef cub::BlockScan<int, TB> BS;
    __shared__ typename BS::TempStorage ts;
    int l = blockIdx.x;
    int run = 0;
    for (int s = 0; s < B; s += TB) {
        int idx = s + threadIdx.x;
        int v = (idx < B) ? g_blk[l * B + idx] : 0;
        int ex, agg;
        BS(ts).ExclusiveSum(v, ex, agg);
        __syncthreads();
        if (idx < B) g_blk[l * B + idx] = run + ex;
        run += agg;
        __syncthreads();
    }
    if (threadIdx.x == 0) g_counts[l] = run + 1;
}

// all 16 layers: rank = base + prefix of (L<=l); OR child bit into flags
__global__ void k_flags_all(int n, int B) {
    __shared__ int s_base[16];
    __shared__ int s_w[16][8];
    int b = blockIdx.x;
    if (threadIdx.x < 16) s_base[threadIdx.x] = g_blk[threadIdx.x * B + b];
    int i = b * TB + threadIdx.x;
    int lane = threadIdx.x & 31, wid = threadIdx.x >> 5;
    bool act = i < n;
    int L = act ? (int)g_L[i] : 100;
    unsigned u = act ? g_sorted[i] : 0u;
    unsigned lm_le = (lane == 31) ? FULLMASK : ((2u << lane) - 1);

    unsigned bal[16];
    #pragma unroll
    for (int l = 0; l < 16; l++) {
        bal[l] = __ballot_sync(FULLMASK, L <= l);
        if (lane == 0) s_w[l][wid] = __popc(bal[l]);
    }
    __syncthreads();
    if (threadIdx.x < 16) {
        int l = threadIdx.x, run = 0;
        #pragma unroll
        for (int w = 0; w < 8; w++) { int v = s_w[l][w]; s_w[l][w] = run; run += v; }
    }
    __syncthreads();

    #pragma unroll
    for (int l = 0; l < 16; l++) {
        int r = act ? (s_base[l] + s_w[l][wid] + __popc(bal[l] & lm_le))
                    : 0x7fffffff;
        unsigned v = 1u << child_at(u, l);
        // warp-segmented inclusive OR over equal ranks (ranks nondecreasing)
        #pragma unroll
        for (int o = 1; o < 32; o <<= 1) {
            unsigned uv = __shfl_up_sync(FULLMASK, v, o);
            int ur = __shfl_up_sync(FULLMASK, r, o);
            if (lane >= o && ur == r) v |= uv;
        }
        int rn = __shfl_down_sync(FULLMASK, r, 1);
        if (act && (lane == 31 || rn != r)) {
            size_t byte = (size_t)l * n + r;
            atomicOr(&g_flagsb[byte >> 2], v << ((byte & 3) * 8));
        }
    }
}

// byte-packed flags -> float32 output (4 per thread)
__global__ void k_flags_to_float(float* __restrict__ out, size_t words) {
    size_t w = (size_t)blockIdx.x * blockDim.x + threadIdx.x;
    if (w < words) {
        unsigned v = g_flagsb[w];
        float4 f;
        f.x = (float)(v & 0xff);
        f.y = (float)((v >> 8) & 0xff);
        f.z = (float)((v >> 16) & 0xff);
        f.w = (float)(v >> 24);
        ((float4*)out)[w] = f;
    }
}

__global__ void k_tail(float* __restrict__ out, int n) {
    size_t base = (size_t)16 * n;
    int t = threadIdx.x;
    if (t < 16)      out[base + t] = (float)g_counts[t];
    else if (t < 64) out[base + t] = (float)g_perm[t - 16];
    else if (t < 67) out[base + t] = g_off[t - 64];
    else if (t < 70) out[base + t] = g_scl[t - 67];
}

// ---------------- launcher ----------------

extern "C" void kernel_launch(void* const* d_in, const int* in_sizes, int n_in,
                              void* d_out, int out_size) {
    const float* X = (const float*)d_in[0];
    int n = in_sizes[0] / 3;
    if (n > NMAX) n = NMAX;
    float* out = (float*)d_out;

    void *p_code, *p_sorted, *p_flagsb, *p_temp;
    cudaGetSymbolAddress(&p_code, g_code);
    cudaGetSymbolAddress(&p_sorted, g_sorted);
    cudaGetSymbolAddress(&p_flagsb, g_flagsb);
    cudaGetSymbolAddress(&p_temp, g_temp);

    int blocks = (n + TB - 1) / TB;
    int B = blocks;

    k_init<<<1, 64>>>();
    k_minmax<<<blocks, TB>>>(X, n);
    k_params<<<1, 32>>>();
    k_quant<<<blocks, TB>>>(X, n);
    k_perm<<<1, 32>>>(n);
    k_remap<<<blocks, TB>>>(n);

    size_t tb = sizeof(g_temp);
    cub::DeviceRadixSort::SortKeys(p_temp, tb,
                                   (const unsigned int*)p_code,
                                   (unsigned int*)p_sorted,
                                   n, 0, 32, (cudaStream_t)0);

    k_L<<<blocks, TB>>>(n);
    cudaMemsetAsync(p_flagsb, 0, (size_t)16 * n, 0);
    k_blkcnt<<<blocks, TB>>>(n, B);
    k_blkscan<<<16, TB>>>(B);
    k_flags_all<<<blocks, TB>>>(n, B);

    size_t words = (size_t)16 * n / 4;   // 16n always divisible by 4
    int fb = (int)((words + TB - 1) / TB);
    k_flags_to_float<<<fb, TB>>>(out, words);
    if ((long long)out_size >= (long long)16 * n + 70)
        k_tail<<<1, 128>>>(out, n);
}